// round 1
// baseline (speedup 1.0000x reference)
#include <cuda_runtime.h>
#include <math.h>

#define C_OUT 64
#define C_IN  10
#define MPTS  32
#define PPB   4   // pillars per block (256 threads)

// Per-launch folded constants (no cudaMalloc allowed -> __device__ globals)
__device__ float g_A0[C_OUT];
__device__ float g_A1[C_OUT];
__device__ float g_A2[C_OUT];
__device__ float g_A3[C_OUT];
__device__ float g_W4[C_OUT];
__device__ float g_W5[C_OUT];
__device__ float g_W6[C_OUT];
__device__ float g_W7[C_OUT];
__device__ float g_W8[C_OUT];
__device__ float g_W9[C_OUT];
__device__ float g_bp[C_OUT];
__device__ float g_gb[C_OUT];   // gelu(bias) = contribution of masked rows

__device__ __forceinline__ float gelu_exact(float x) {
    return 0.5f * x * (1.0f + erff(x * 0.70710678118654752f));
}

// Fold BN (running stats, gamma, beta) into the linear weights, and exploit
// the affine structure of the augmented channels:
//   feats = [f0,f1,f2,f3, f0-mx,f1-my,f2-mz, f0-px,f1-py,f2-pz]
//   x[m,o] = f0*(w0+w4+w7)+f1*(w1+w5+w8)+f2*(w2+w6+w9)+f3*w3
//            - mx*w4-my*w5-mz*w6 - px*w7-py*w8-pz*w9 + bias
__global__ void pfn_precompute(const float* __restrict__ W,
                               const float* __restrict__ gamma,
                               const float* __restrict__ beta,
                               const float* __restrict__ rmean,
                               const float* __restrict__ rvar) {
    int o = threadIdx.x;
    if (o >= C_OUT) return;
    float s  = rsqrtf(rvar[o] + 1e-3f) * gamma[o];
    float bp = beta[o] - rmean[o] * s;
    float w[C_IN];
#pragma unroll
    for (int c = 0; c < C_IN; c++) w[c] = W[o * C_IN + c] * s;
    g_A0[o] = w[0] + w[4] + w[7];
    g_A1[o] = w[1] + w[5] + w[8];
    g_A2[o] = w[2] + w[6] + w[9];
    g_A3[o] = w[3];
    g_W4[o] = w[4]; g_W5[o] = w[5]; g_W6[o] = w[6];
    g_W7[o] = w[7]; g_W8[o] = w[8]; g_W9[o] = w[9];
    g_bp[o] = bp;
    g_gb[o] = gelu_exact(bp);
}

__global__ __launch_bounds__(PPB * 64)
void pfn_main(const float4* __restrict__ feats,     // [N, 32] float4
              const int*    __restrict__ num_points, // [N]
              const int4*   __restrict__ coors,      // [N] int4 (z,y,x,_)
              float*        __restrict__ out,        // [N, 64]
              int N) {
    __shared__ float4 sf[PPB][MPTS];
    __shared__ float  smean[PPB][3];

    const int lp = threadIdx.x >> 6;   // local pillar 0..3
    const int o  = threadIdx.x & 63;   // output channel
    const int p  = blockIdx.x * PPB + lp;
    const bool valid = (p < N);

    int K = 1;
    if (valid) K = num_points[p];

    // Stage this pillar's 32 float4 rows; even warps (o<32) do it (coalesced 512B)
    if (valid && o < MPTS) {
        float4 row = feats[(size_t)p * MPTS + o];
        sf[lp][o] = row;
        // xyz sum over ALL 32 rows (reference sums unmasked rows too), / K
        float sx = row.x, sy = row.y, sz = row.z;
#pragma unroll
        for (int off = 16; off; off >>= 1) {
            sx += __shfl_xor_sync(0xffffffffu, sx, off);
            sy += __shfl_xor_sync(0xffffffffu, sy, off);
            sz += __shfl_xor_sync(0xffffffffu, sz, off);
        }
        if (o == 0) {
            float fK = (float)K;
            smean[lp][0] = sx / fK;
            smean[lp][1] = sy / fK;
            smean[lp][2] = sz / fK;
        }
    }
    __syncthreads();
    if (!valid) return;

    const float A0 = g_A0[o], A1 = g_A1[o], A2 = g_A2[o], A3 = g_A3[o];

    const int4 cr = coors[p];
    // VX=VY=0.2, VZ=4.0; X_OFF=0.1, Y_OFF=-39.9, Z_OFF=-1.0
    // coors columns: [:,0]=cz, [:,1]=cy, [:,2]=cx
    const float px = (float)cr.z * 0.2f + 0.1f;
    const float py = (float)cr.y * 0.2f + (-39.9f);
    const float pz = (float)cr.x * 4.0f + (-1.0f);

    const float mx = smean[lp][0], my = smean[lp][1], mz = smean[lp][2];

    float cst = g_bp[o];
    cst = fmaf(-mx, g_W4[o], cst);
    cst = fmaf(-my, g_W5[o], cst);
    cst = fmaf(-mz, g_W6[o], cst);
    cst = fmaf(-px, g_W7[o], cst);
    cst = fmaf(-py, g_W8[o], cst);
    cst = fmaf(-pz, g_W9[o], cst);

    // Track min & max of the per-point dot; const shift commutes with min/max.
    float dmax = -3.402823466e38f;
    float dmin =  3.402823466e38f;
#pragma unroll 4
    for (int m = 0; m < K; m++) {
        float4 f = sf[lp][m];                  // broadcast LDS.128
        float d = f.x * A0;
        d = fmaf(f.y, A1, d);
        d = fmaf(f.z, A2, d);
        d = fmaf(f.w, A3, d);
        dmax = fmaxf(dmax, d);
        dmin = fminf(dmin, d);
    }

    // GELU is unimodal (decreasing then increasing) => max over set of
    // gelu(x_i) = max(gelu(min), gelu(max)). Masked rows contribute gelu(bias).
    float r = fmaxf(gelu_exact(dmax + cst), gelu_exact(dmin + cst));
    if (K < MPTS) r = fmaxf(r, g_gb[o]);
    out[(size_t)p * C_OUT + o] = r;
}

extern "C" void kernel_launch(void* const* d_in, const int* in_sizes, int n_in,
                              void* d_out, int out_size) {
    const float* features   = (const float*)d_in[0];
    const int*   num_points = (const int*)d_in[1];
    const int*   coors      = (const int*)d_in[2];
    const float* W          = (const float*)d_in[3];
    const float* gamma      = (const float*)d_in[4];
    const float* beta       = (const float*)d_in[5];
    const float* rmean      = (const float*)d_in[6];
    const float* rvar       = (const float*)d_in[7];
    float* out = (float*)d_out;

    const int N = in_sizes[0] / (MPTS * 4);

    pfn_precompute<<<1, C_OUT>>>(W, gamma, beta, rmean, rvar);

    int blocks = (N + PPB - 1) / PPB;
    pfn_main<<<blocks, PPB * 64>>>((const float4*)features, num_points,
                                   (const int4*)coors, out, N);
}

// round 2
// speedup vs baseline: 1.3723x; 1.3723x over previous
#include <cuda_runtime.h>
#include <math.h>

#define MPTS 32
#define PPB  8     // pillars per block, 1 warp per pillar (256 threads)

// Precomputed constants, packed per channel-pair t: (val[2t], val[2t+1])
__device__ float2 g_pA[4][32];   // folded A0..A3 (dot coefficients)
__device__ float2 g_pW[6][32];   // W4..W9 (for mean/center const folding)
__device__ float2 g_pbp[32];     // BN-folded bias
__device__ float2 g_pgb[32];     // gelu(bias) = masked-row contribution

__device__ __forceinline__ float gelu_exact(float x) {
    return 0.5f * x * (1.0f + erff(x * 0.70710678118654752f));
}

// ---- f32x2 packed helpers (sm_103a) ----
__device__ __forceinline__ unsigned long long fma2(unsigned long long a,
                                                   unsigned long long b,
                                                   unsigned long long c) {
    unsigned long long d;
    asm("fma.rn.f32x2 %0, %1, %2, %3;" : "=l"(d) : "l"(a), "l"(b), "l"(c));
    return d;
}
__device__ __forceinline__ unsigned long long mul2(unsigned long long a,
                                                   unsigned long long b) {
    unsigned long long d;
    asm("mul.rn.f32x2 %0, %1, %2;" : "=l"(d) : "l"(a), "l"(b));
    return d;
}
__device__ __forceinline__ unsigned long long pack2(float lo, float hi) {
    unsigned long long d;
    asm("mov.b64 %0, {%1, %2};" : "=l"(d) : "f"(lo), "f"(hi));
    return d;
}
__device__ __forceinline__ void unpack2(unsigned long long v, float& lo, float& hi) {
    asm("mov.b64 {%0, %1}, %2;" : "=f"(lo), "=f"(hi) : "l"(v));
}

// Fold BN into W; exploit affine structure of augmented channels:
//   x[m,o] = f0*(w0+w4+w7)+f1*(w1+w5+w8)+f2*(w2+w6+w9)+f3*w3
//            - mx*w4-my*w5-mz*w6 - px*w7-py*w8-pz*w9 + bias
__global__ void pfn_precompute(const float* __restrict__ W,
                               const float* __restrict__ gamma,
                               const float* __restrict__ beta,
                               const float* __restrict__ rmean,
                               const float* __restrict__ rvar) {
    int o = threadIdx.x;
    if (o >= 64) return;
    float s  = rsqrtf(rvar[o] + 1e-3f) * gamma[o];
    float bp = beta[o] - rmean[o] * s;
    float w[10];
#pragma unroll
    for (int c = 0; c < 10; c++) w[c] = W[o * 10 + c] * s;
    int t = o >> 1, h = o & 1;
    ((float*)&g_pA[0][t])[h] = w[0] + w[4] + w[7];
    ((float*)&g_pA[1][t])[h] = w[1] + w[5] + w[8];
    ((float*)&g_pA[2][t])[h] = w[2] + w[6] + w[9];
    ((float*)&g_pA[3][t])[h] = w[3];
#pragma unroll
    for (int c = 0; c < 6; c++) ((float*)&g_pW[c][t])[h] = w[4 + c];
    ((float*)&g_pbp[t])[h] = bp;
    ((float*)&g_pgb[t])[h] = gelu_exact(bp);
}

__global__ __launch_bounds__(PPB * 32)
void pfn_main(const float4* __restrict__ feats,      // [N,32] float4
              const int*    __restrict__ num_points,  // [N]
              const int4*   __restrict__ coors,       // [N] (z,y,x,_)
              float*        __restrict__ out,         // [N,64]
              int N) {
    __shared__ float sdat[PPB][4][MPTS];   // transposed SoA per pillar

    const int lp   = threadIdx.x >> 5;
    const int lane = threadIdx.x & 31;
    const int p    = blockIdx.x * PPB + lp;
    if (p >= N) return;                     // whole warp exits together

    const int K = num_points[p];

    // ---- stage: coalesced 512B row load per warp ----
    float4 row = feats[(size_t)p * MPTS + lane];

    // mean over ALL 32 raw rows (reference sums unmasked garbage too), / K
    float sx = row.x, sy = row.y, sz = row.z;
#pragma unroll
    for (int off = 16; off; off >>= 1) {
        sx += __shfl_xor_sync(0xffffffffu, sx, off);
        sy += __shfl_xor_sync(0xffffffffu, sy, off);
        sz += __shfl_xor_sync(0xffffffffu, sz, off);
    }
    const float fK = (float)K;
    const float mx = sx / fK, my = sy / fK, mz = sz / fK;

    // pad invalid rows with a COPY of row 0 (K>=1 always): duplicates a valid
    // point's d-value, so min/max are unaffected by padding.
    float r0x = __shfl_sync(0xffffffffu, row.x, 0);
    float r0y = __shfl_sync(0xffffffffu, row.y, 0);
    float r0z = __shfl_sync(0xffffffffu, row.z, 0);
    float r0w = __shfl_sync(0xffffffffu, row.w, 0);
    if (lane >= K) { row.x = r0x; row.y = r0y; row.z = r0z; row.w = r0w; }
    sdat[lp][0][lane] = row.x;
    sdat[lp][1][lane] = row.y;
    sdat[lp][2][lane] = row.z;
    sdat[lp][3][lane] = row.w;
    __syncwarp();

    // ---- per-thread constants: channels (2*lane, 2*lane+1) ----
    const float2 A0 = g_pA[0][lane], A1 = g_pA[1][lane];
    const float2 A2 = g_pA[2][lane], A3 = g_pA[3][lane];
    const float2 W4 = g_pW[0][lane], W5 = g_pW[1][lane], W6 = g_pW[2][lane];
    const float2 W7 = g_pW[3][lane], W8 = g_pW[4][lane], W9 = g_pW[5][lane];
    const float2 bp = g_pbp[lane],   gb = g_pgb[lane];

    const int4 cr = coors[p];
    // VX=VY=0.2, VZ=4.0; X_OFF=0.1, Y_OFF=-39.9, Z_OFF=-1.0; cols (cz,cy,cx)
    const float px = (float)cr.z * 0.2f + 0.1f;
    const float py = (float)cr.y * 0.2f + (-39.9f);
    const float pz = (float)cr.x * 4.0f + (-1.0f);

    float cst0 = bp.x, cst1 = bp.y;
    cst0 = fmaf(-mx, W4.x, cst0); cst1 = fmaf(-mx, W4.y, cst1);
    cst0 = fmaf(-my, W5.x, cst0); cst1 = fmaf(-my, W5.y, cst1);
    cst0 = fmaf(-mz, W6.x, cst0); cst1 = fmaf(-mz, W6.y, cst1);
    cst0 = fmaf(-px, W7.x, cst0); cst1 = fmaf(-px, W7.y, cst1);
    cst0 = fmaf(-py, W8.x, cst0); cst1 = fmaf(-py, W8.y, cst1);
    cst0 = fmaf(-pz, W9.x, cst0); cst1 = fmaf(-pz, W9.y, cst1);

    // duplicated packed coefficients (built once; used every iter)
    const unsigned long long a0c0 = pack2(A0.x, A0.x), a0c1 = pack2(A0.y, A0.y);
    const unsigned long long a1c0 = pack2(A1.x, A1.x), a1c1 = pack2(A1.y, A1.y);
    const unsigned long long a2c0 = pack2(A2.x, A2.x), a2c1 = pack2(A2.y, A2.y);
    const unsigned long long a3c0 = pack2(A3.x, A3.x), a3c1 = pack2(A3.y, A3.y);

    const float INF = 3.402823466e38f;
    float mx0a = -INF, mx0b = -INF, mn0a = INF, mn0b = INF;   // channel 0
    float mx1a = -INF, mx1b = -INF, mn1a = INF, mn1b = INF;   // channel 1

    const int T = (K + 3) >> 2;
#pragma unroll 2
    for (int i = 0; i < T; i++) {
        // 4 points of each component as (m,m+1),(m+2,m+3) f32x2 pairs
        ulonglong2 X = *(const ulonglong2*)&sdat[lp][0][4 * i];
        ulonglong2 Y = *(const ulonglong2*)&sdat[lp][1][4 * i];
        ulonglong2 Z = *(const ulonglong2*)&sdat[lp][2][4 * i];
        ulonglong2 Wv = *(const ulonglong2*)&sdat[lp][3][4 * i];

        // channel 0
        unsigned long long d0a = fma2(X.x, a0c0, fma2(Y.x, a1c0, fma2(Z.x, a2c0, mul2(Wv.x, a3c0))));
        unsigned long long d0b = fma2(X.y, a0c0, fma2(Y.y, a1c0, fma2(Z.y, a2c0, mul2(Wv.y, a3c0))));
        // channel 1
        unsigned long long d1a = fma2(X.x, a0c1, fma2(Y.x, a1c1, fma2(Z.x, a2c1, mul2(Wv.x, a3c1))));
        unsigned long long d1b = fma2(X.y, a0c1, fma2(Y.y, a1c1, fma2(Z.y, a2c1, mul2(Wv.y, a3c1))));

        float l, h;
        unpack2(d0a, l, h); mx0a = fmaxf(mx0a, l); mn0a = fminf(mn0a, l);
                            mx0b = fmaxf(mx0b, h); mn0b = fminf(mn0b, h);
        unpack2(d0b, l, h); mx0a = fmaxf(mx0a, l); mn0a = fminf(mn0a, l);
                            mx0b = fmaxf(mx0b, h); mn0b = fminf(mn0b, h);
        unpack2(d1a, l, h); mx1a = fmaxf(mx1a, l); mn1a = fminf(mn1a, l);
                            mx1b = fmaxf(mx1b, h); mn1b = fminf(mn1b, h);
        unpack2(d1b, l, h); mx1a = fmaxf(mx1a, l); mn1a = fminf(mn1a, l);
                            mx1b = fmaxf(mx1b, h); mn1b = fminf(mn1b, h);
    }

    const float dmax0 = fmaxf(mx0a, mx0b), dmin0 = fminf(mn0a, mn0b);
    const float dmax1 = fmaxf(mx1a, mx1b), dmin1 = fminf(mn1a, mn1b);

    // gelu unimodal => max over gelu = max(gelu(min), gelu(max));
    // masked rows contribute exactly gelu(bias).
    float r0 = fmaxf(gelu_exact(dmax0 + cst0), gelu_exact(dmin0 + cst0));
    float r1 = fmaxf(gelu_exact(dmax1 + cst1), gelu_exact(dmin1 + cst1));
    if (K < MPTS) { r0 = fmaxf(r0, gb.x); r1 = fmaxf(r1, gb.y); }

    *(float2*)&out[(size_t)p * 64 + 2 * lane] = make_float2(r0, r1);
}

extern "C" void kernel_launch(void* const* d_in, const int* in_sizes, int n_in,
                              void* d_out, int out_size) {
    const float* features   = (const float*)d_in[0];
    const int*   num_points = (const int*)d_in[1];
    const int*   coors      = (const int*)d_in[2];
    const float* W          = (const float*)d_in[3];
    const float* gamma      = (const float*)d_in[4];
    const float* beta       = (const float*)d_in[5];
    const float* rmean      = (const float*)d_in[6];
    const float* rvar       = (const float*)d_in[7];
    float* out = (float*)d_out;

    const int N = in_sizes[0] / (MPTS * 4);

    pfn_precompute<<<1, 64>>>(W, gamma, beta, rmean, rvar);

    int blocks = (N + PPB - 1) / PPB;
    pfn_main<<<blocks, PPB * 32>>>((const float4*)features, num_points,
                                   (const int4*)coors, out, N);
}